// round 13
// baseline (speedup 1.0000x reference)
#include <cuda_runtime.h>
#include <math_constants.h>
#include <stdint.h>

// attention_FCN: B=512, S=512, F=128, H1=80, H2=40
// din@W2 = qpre(b) + f @ Weff(b),  Weff = (W2b - W2c) + diag(q_b) @ W2d
// Round 13: producer/consumer warp specialization. 384 thr/CTA, 1 CTA/SM.
//  warps 0-7  (256 thr): GEMM1 4x5 f32x2, cp.async facts double-buffer,
//                        h1 double-buffer producer.
//  warps 8-11 (128 thr): GEMM2 4x5, scores, online softmax, epilogue (global).
// Named-barrier FULL/EMPTY handshake; S split across 2 CTAs + flash combine.

#define Bn   512
#define Sn   512
#define Fn   128
#define H1n  80
#define H2n  40
#define TSn  64
#define NT   4          // tiles per CTA (S/2 = 256)
#define FSTRIDE 132
#define WS      132
#define H1S     84
#define W3S     80
#define PARTW   132
#define PADV (-4294967295.0f)

// named barrier ids / counts
#define BAR_FULL0 1
#define BAR_FULL1 2
#define BAR_EMPTY0 3
#define BAR_EMPTY1 4
#define BAR_PROD  5
#define BAR_CONS  6

__device__ float g_part[Bn * 2 * PARTW];

__device__ __forceinline__ unsigned long long pk2(float lo, float hi) {
    unsigned long long r;
    asm("mov.b64 %0, {%1,%2};" : "=l"(r) : "f"(lo), "f"(hi));
    return r;
}
__device__ __forceinline__ float2 upk2(unsigned long long v) {
    float2 r;
    asm("mov.b64 {%0,%1}, %2;" : "=f"(r.x), "=f"(r.y) : "l"(v));
    return r;
}
#define FMA2(d, a, b) \
    asm("fma.rn.f32x2 %0, %1, %2, %0;" : "+l"(d) : "l"(a), "l"(b))

__device__ __forceinline__ float fsigmoid(float x) {
    return __fdividef(1.f, 1.f + __expf(-x));
}
__device__ __forceinline__ uint32_t smem_u32(const void* p) {
    uint32_t a;
    asm("{ .reg .u64 t; cvta.to.shared.u64 t, %1; cvt.u32.u64 %0, t; }"
        : "=r"(a) : "l"(p));
    return a;
}
__device__ __forceinline__ void cpa16(uint32_t dst, const float* src) {
    asm volatile("cp.async.cg.shared.global [%0], [%1], 16;"
                 :: "r"(dst), "l"(src) : "memory");
}
#define CPA_COMMIT() asm volatile("cp.async.commit_group;" ::: "memory")
#define CPA_WAIT(n)  asm volatile("cp.async.wait_group %0;" :: "n"(n) : "memory")
#define BSYNC(id, cnt) \
    asm volatile("bar.sync %0, %1;" :: "r"(id), "r"(cnt) : "memory")
#define BARRIVE(id, cnt) \
    asm volatile("bar.arrive %0, %1;" :: "r"(id), "r"(cnt) : "memory")

// ---------------------------------------------------------------------------
__global__ __launch_bounds__(384, 1) void din_kernel(
    const float* __restrict__ query,
    const float* __restrict__ facts,
    const int*   __restrict__ mask,
    const float* __restrict__ W1,
    const float* __restrict__ b1,
    const float* __restrict__ alpha,
    const float* __restrict__ W2,
    const float* __restrict__ b2,
    const float* __restrict__ W3,
    const float* __restrict__ b3,
    const float* __restrict__ W4,
    const float* __restrict__ b4)
{
    extern __shared__ float dyn[];
    float* fsm0  = dyn;                         // 64*132
    float* fsm1  = fsm0 + TSn * FSTRIDE;        // 64*132
    float* weffT = fsm1 + TSn * FSTRIDE;        // 80*132 (k-major)
    float* h1b0  = weffT + H1n * WS;            // 64*84
    float* h1b1  = h1b0 + TSn * H1S;            // 64*84
    float* w3T   = h1b1 + TSn * H1S;            // 40*80  (k-major)

    __shared__ float qsm[Fn];
    __shared__ float qprem[H1n];
    __shared__ float w4sm[H2n];
    __shared__ float b3sm[H2n];
    __shared__ float psm[4 * TSn];
    __shared__ float sbuf[TSn];
    __shared__ float wsm[TSn];
    __shared__ float red[2];
    __shared__ float s_m, s_l, s_scale, s_b4;

    const int cta  = blockIdx.x;
    const int b    = cta >> 1;
    const int half = cta & 1;
    const int tid  = threadIdx.x;
    const float* factsb = facts + ((size_t)b * Sn + half * (Sn / 2)) * Fn;
    const int    mbase  = b * Sn + half * (Sn / 2);

    float* fsmBuf[2] = { fsm0, fsm1 };
    float* h1Buf[2]  = { h1b0, h1b1 };

    // ---- producers: kick off cp.async for facts tiles 0 and 1 ----
    if (tid < 256) {
#pragma unroll
        for (int it = 0; it < 8; it++) {
            const int idx = it * 256 + tid;
            const int row = idx >> 5, c4 = idx & 31;
            cpa16(smem_u32(fsm0 + row * FSTRIDE + c4 * 4), factsb + idx * 4);
        }
        CPA_COMMIT();
#pragma unroll
        for (int it = 0; it < 8; it++) {
            const int idx = it * 256 + tid;
            const int row = idx >> 5, c4 = idx & 31;
            cpa16(smem_u32(fsm1 + row * FSTRIDE + c4 * 4),
                  factsb + (size_t)TSn * Fn + idx * 4);
        }
        CPA_COMMIT();
    }

    // ---- prologue (all 384 threads) ----
    if (tid < Fn) qsm[tid] = query[b * Fn + tid];
    if (tid == 0) { s_m = -CUDART_INF_F; s_l = 0.f; s_b4 = b4[0]; }
    if (tid >= 256 && tid < 256 + H2n) {
        w4sm[tid - 256] = W4[tid - 256];
        b3sm[tid - 256] = b3[tid - 256];
    }
    __syncthreads();

    float qv = 0.f;
    if (tid < Fn) {               // q = PReLU(query@W1+b1)
        float a0 = b1[tid], a1 = 0.f, a2 = 0.f, a3 = 0.f;
#pragma unroll 4
        for (int k = 0; k < Fn; k += 4) {
            a0 = fmaf(qsm[k + 0], W1[(k + 0) * Fn + tid], a0);
            a1 = fmaf(qsm[k + 1], W1[(k + 1) * Fn + tid], a1);
            a2 = fmaf(qsm[k + 2], W1[(k + 2) * Fn + tid], a2);
            a3 = fmaf(qsm[k + 3], W1[(k + 3) * Fn + tid], a3);
        }
        const float acc = (a0 + a1) + (a2 + a3);
        qv = (acc >= 0.f) ? acc : alpha[tid] * acc;
    } else if (tid >= 128) {      // w3T[h2][k] = W3[k][h2] (256 threads)
        for (int i = tid - 128; i < H1n * H2n; i += 256) {
            const int h2 = i % H2n, k = i / H2n;
            w3T[h2 * W3S + k] = W3[i];
        }
    }
    __syncthreads();
    if (tid < Fn) qsm[tid] = qv;
    __syncthreads();

    if (tid < H1n) {              // qpre
        float a0 = b2[tid], a1 = 0.f;
#pragma unroll 4
        for (int k = 0; k < Fn; k += 2) {
            a0 = fmaf(qsm[k+0], W2[(k+0)*H1n + tid] + W2[(2*Fn + k+0)*H1n + tid], a0);
            a1 = fmaf(qsm[k+1], W2[(k+1)*H1n + tid] + W2[(2*Fn + k+1)*H1n + tid], a1);
        }
        qprem[tid] = a0 + a1;
    }
    for (int i = tid; i < Fn * H1n; i += 384) {   // weffT (k-major)
        const int k = i / H1n, h = i - k * H1n;
        const float wbc = W2[(Fn + k) * H1n + h] - W2[(2 * Fn + k) * H1n + h];
        const float wd  = W2[(3 * Fn + k) * H1n + h];
        weffT[h * WS + k] = fmaf(qsm[k], wd, wbc);
    }
    __syncthreads();   // last CTA-wide sync before the pipeline

    // =======================================================================
    if (tid < 256) {
        // ---------------- PRODUCER: GEMM1 into h1Buf[t&1] ------------------
        const int tx = tid & 15;          // cols tx*5..+4
        const int ty = tid >> 4;          // rows ty*4..+3
        const float* wb = weffT + (tx * 5) * WS;

        for (int t = 0; t < NT; t++) {
            const int buf = t & 1;
            if (t >= 2)                    // wait h1Buf[buf] consumed
                BSYNC((buf ? BAR_EMPTY1 : BAR_EMPTY0), 384);
            if (t < NT - 1) CPA_WAIT(1); else CPA_WAIT(0);

            unsigned long long acc2[4][5];
#pragma unroll
            for (int i = 0; i < 4; i++)
#pragma unroll
                for (int j = 0; j < 5; j++)
                    acc2[i][j] = pk2(qprem[tx * 5 + j], 0.f);

            const float* fr = fsmBuf[buf] + (ty * 4) * FSTRIDE;
#pragma unroll 2
            for (int k = 0; k < Fn; k += 4) {
                ulonglong2 av[4], bv[5];
#pragma unroll
                for (int i = 0; i < 4; i++)
                    av[i] = *(const ulonglong2*)(fr + i * FSTRIDE + k);
#pragma unroll
                for (int j = 0; j < 5; j++)
                    bv[j] = *(const ulonglong2*)(wb + j * WS + k);
#pragma unroll
                for (int i = 0; i < 4; i++)
#pragma unroll
                    for (int j = 0; j < 5; j++) {
                        FMA2(acc2[i][j], av[i].x, bv[j].x);
                        FMA2(acc2[i][j], av[i].y, bv[j].y);
                    }
            }

            // all producer reads of fsmBuf[buf] done -> safe to refill
            BSYNC(BAR_PROD, 256);
            if (t + 2 < NT) {
                const float* nsrc = factsb + (size_t)(t + 2) * TSn * Fn;
#pragma unroll
                for (int it = 0; it < 8; it++) {
                    const int idx = it * 256 + tid;
                    const int row = idx >> 5, c4 = idx & 31;
                    cpa16(smem_u32(fsmBuf[buf] + row * FSTRIDE + c4 * 4),
                          nsrc + idx * 4);
                }
                CPA_COMMIT();
            }

            float* hb = h1Buf[buf];
#pragma unroll
            for (int i = 0; i < 4; i++)
#pragma unroll
                for (int j = 0; j < 5; j++) {
                    const float2 v = upk2(acc2[i][j]);
                    hb[(ty * 4 + i) * H1S + tx * 5 + j] = fsigmoid(v.x + v.y);
                }
            BARRIVE((buf ? BAR_FULL1 : BAR_FULL0), 384);   // h1 ready
        }
    } else {
        // ---------------- CONSUMER: GEMM2 / softmax / epilogue -------------
        const int ctid = tid - 256;          // 0..127
        const int lane = ctid & 31;
        const int rowg = ctid & 15;          // rows rowg*4..+3
        const int colg = ctid >> 4;          // cols colg*5..+4
        const float* wc = w3T + (colg * 5) * W3S;
        float racc = 0.f;

        for (int t = 0; t < NT; t++) {
            const int buf = t & 1;
            BSYNC((buf ? BAR_FULL1 : BAR_FULL0), 384);     // wait h1

            // ---- GEMM2: 4x5 per thread over h1Buf[buf] ----
            {
                unsigned long long acc2[4][5];
#pragma unroll
                for (int j = 0; j < 5; j++) {
                    const unsigned long long z = pk2(b3sm[colg * 5 + j], 0.f);
#pragma unroll
                    for (int i = 0; i < 4; i++) acc2[i][j] = z;
                }
                const float* hr = h1Buf[buf] + (rowg * 4) * H1S;
#pragma unroll 2
                for (int k = 0; k < H1n; k += 4) {
                    ulonglong2 av[4], bv[5];
#pragma unroll
                    for (int i = 0; i < 4; i++)
                        av[i] = *(const ulonglong2*)(hr + i * H1S + k);
#pragma unroll
                    for (int j = 0; j < 5; j++)
                        bv[j] = *(const ulonglong2*)(wc + j * W3S + k);
#pragma unroll
                    for (int i = 0; i < 4; i++)
#pragma unroll
                        for (int j = 0; j < 5; j++) {
                            FMA2(acc2[i][j], av[i].x, bv[j].x);
                            FMA2(acc2[i][j], av[i].y, bv[j].y);
                        }
                }
#pragma unroll
                for (int i = 0; i < 4; i++) {
                    float p = 0.f;
#pragma unroll
                    for (int j = 0; j < 5; j++) {
                        const float2 v = upk2(acc2[i][j]);
                        p = fmaf(fsigmoid(v.x + v.y), w4sm[colg * 5 + j], p);
                    }
                    p += __shfl_xor_sync(0xffffffffu, p, 16);
                    if ((ctid & 16) == 0)
                        psm[(ctid >> 5) * TSn + rowg * 4 + i] = p;
                }
            }
            BSYNC(BAR_CONS, 128);            // psm ready; h1 reads done
            if (t + 2 < NT)                  // release h1Buf[buf] to producer
                BARRIVE((buf ? BAR_EMPTY1 : BAR_EMPTY0), 384);

            // ---- scores + mask ----
            if (ctid < TSn) {
                const float sc = psm[ctid] + psm[TSn + ctid]
                               + psm[2 * TSn + ctid] + psm[3 * TSn + ctid] + s_b4;
                sbuf[ctid] = (mask[mbase + t * TSn + ctid] == 1) ? sc : PADV;
            }
            BSYNC(BAR_CONS, 128);

            // ---- tile max -> running max/scale ----
            if (ctid < 32) {
                float m4 = fmaxf(sbuf[ctid], sbuf[ctid + 32]);
#pragma unroll
                for (int off = 16; off; off >>= 1)
                    m4 = fmaxf(m4, __shfl_xor_sync(0xffffffffu, m4, off));
                if (ctid == 0) {
                    const float nm = fmaxf(s_m, m4);
                    s_scale = __expf(s_m - nm);
                    s_m = nm;
                }
            }
            BSYNC(BAR_CONS, 128);

            // ---- weights + tile sum ----
            float wv = 0.f;
            if (ctid < TSn) {
                wv = __expf(sbuf[ctid] - s_m);
                wsm[ctid] = wv;
            }
#pragma unroll
            for (int off = 16; off; off >>= 1)
                wv += __shfl_xor_sync(0xffffffffu, wv, off);
            if (ctid < TSn && lane == 0) red[ctid >> 5] = wv;
            BSYNC(BAR_CONS, 128);
            if (ctid == 0) s_l = s_l * s_scale + red[0] + red[1];

            // ---- epilogue: weighted facts from global (L2-hot) ----
            {
                const float* fb = factsb + (size_t)(t * TSn) * Fn + ctid;
                float a0 = racc * s_scale, a1 = 0.f, a2 = 0.f, a3 = 0.f;
#pragma unroll 4
                for (int s = 0; s < TSn; s += 4) {
                    a0 = fmaf(wsm[s + 0], fb[(size_t)(s + 0) * Fn], a0);
                    a1 = fmaf(wsm[s + 1], fb[(size_t)(s + 1) * Fn], a1);
                    a2 = fmaf(wsm[s + 2], fb[(size_t)(s + 2) * Fn], a2);
                    a3 = fmaf(wsm[s + 3], fb[(size_t)(s + 3) * Fn], a3);
                }
                racc = (a0 + a1) + (a2 + a3);
            }
            // wsm is rewritten only after next FULL sync + 2 CONS barriers,
            // all ordered after this point in consumer program order.
        }

        // ---- write flash partial ----
        float* part = g_part + cta * PARTW;
        part[ctid] = racc;
        if (ctid == 0) { part[128] = s_m; part[129] = s_l; }
    }
}

// ---------------------------------------------------------------------------
__global__ __launch_bounds__(128) void combine_kernel(float* __restrict__ out)
{
    const int b = blockIdx.x, tid = threadIdx.x;
    const float* p0 = g_part + (2 * b) * PARTW;
    const float* p1 = g_part + (2 * b + 1) * PARTW;
    const float m0 = p0[128], l0 = p0[129];
    const float m1 = p1[128], l1 = p1[129];
    const float M = fmaxf(m0, m1);
    const float w0 = __expf(m0 - M), w1 = __expf(m1 - M);
    const float denom = w0 * l0 + w1 * l1;
    out[b * Fn + tid] = (w0 * p0[tid] + w1 * p1[tid]) / denom;
}

// ---------------------------------------------------------------------------
extern "C" void kernel_launch(void* const* d_in, const int* in_sizes, int n_in,
                              void* d_out, int out_size)
{
    const float* query = (const float*)d_in[0];
    const float* facts = (const float*)d_in[1];
    const int*   mask  = (const int*)  d_in[2];
    const float* W1    = (const float*)d_in[3];
    const float* b1    = (const float*)d_in[4];
    const float* alpha = (const float*)d_in[5];
    const float* W2    = (const float*)d_in[6];
    const float* b2    = (const float*)d_in[7];
    const float* W3    = (const float*)d_in[8];
    const float* b3    = (const float*)d_in[9];
    const float* W4    = (const float*)d_in[10];
    const float* b4    = (const float*)d_in[11];
    float* out = (float*)d_out;

    const int dyn_smem =
        (2 * TSn * FSTRIDE + H1n * WS + 2 * TSn * H1S + H2n * W3S)
        * (int)sizeof(float);   // 165632 B
    cudaFuncSetAttribute(din_kernel,
                         cudaFuncAttributeMaxDynamicSharedMemorySize, dyn_smem);

    din_kernel<<<Bn * 2, 384, dyn_smem>>>(query, facts, mask, W1, b1, alpha,
                                          W2, b2, W3, b3, W4, b4);
    combine_kernel<<<Bn, 128>>>(out);
}

// round 14
// speedup vs baseline: 1.1723x; 1.1723x over previous
#include <cuda_runtime.h>
#include <math_constants.h>
#include <stdint.h>

// attention_FCN: B=512, S=512, F=128, H1=80, H2=40
// din@W2 = qpre(b) + f @ Weff(b),  Weff = (W2b - W2c) + diag(q_b) @ W2d
// Round 14: R12 skeleton (256 thr, 2 CTA/SM) with
//  - GEMM1 8x5 per-thread tile on low 128 threads (13 loads / 80 MACs-f32x2)
//  - epilogue(t-1) on high 128 threads CONCURRENT with GEMM1(t)
//  - GEMM2 4x5 on high 128, prefetch issued by low 128 in the same phase
//  - single-warp fused softmax (scores+mask+max+exp+sum, no inner syncs)
//  - 3 CTA-wide syncs per tile (was 6)

#define Bn   512
#define Sn   512
#define Fn   128
#define H1n  80
#define H2n  40
#define TSn  64
#define NTn  (Sn / TSn)
#define FSTRIDE 132
#define WS      132
#define H1S     84
#define W3S     80
#define PADV (-4294967295.0f)

__device__ __forceinline__ unsigned long long pk2(float lo, float hi) {
    unsigned long long r;
    asm("mov.b64 %0, {%1,%2};" : "=l"(r) : "f"(lo), "f"(hi));
    return r;
}
__device__ __forceinline__ float2 upk2(unsigned long long v) {
    float2 r;
    asm("mov.b64 {%0,%1}, %2;" : "=f"(r.x), "=f"(r.y) : "l"(v));
    return r;
}
#define FMA2(d, a, b) \
    asm("fma.rn.f32x2 %0, %1, %2, %0;" : "+l"(d) : "l"(a), "l"(b))

__device__ __forceinline__ float fsigmoid(float x) {
    return __fdividef(1.f, 1.f + __expf(-x));
}
__device__ __forceinline__ uint32_t smem_u32(const void* p) {
    uint32_t a;
    asm("{ .reg .u64 t; cvta.to.shared.u64 t, %1; cvt.u32.u64 %0, t; }"
        : "=r"(a) : "l"(p));
    return a;
}
__device__ __forceinline__ void cpa16(uint32_t dst, const float* src) {
    asm volatile("cp.async.cg.shared.global [%0], [%1], 16;"
                 :: "r"(dst), "l"(src) : "memory");
}
#define CPA_COMMIT() asm volatile("cp.async.commit_group;" ::: "memory")
#define CPA_WAIT0()  asm volatile("cp.async.wait_group 0;" ::: "memory")

// ---------------------------------------------------------------------------
__global__ __launch_bounds__(256, 2) void din_kernel(
    const float* __restrict__ query,
    const float* __restrict__ facts,
    const int*   __restrict__ mask,
    const float* __restrict__ W1,
    const float* __restrict__ b1,
    const float* __restrict__ alpha,
    const float* __restrict__ W2,
    const float* __restrict__ b2,
    const float* __restrict__ W3,
    const float* __restrict__ b3,
    const float* __restrict__ W4,
    const float* __restrict__ b4,
    float* __restrict__ out)
{
    extern __shared__ float dyn[];
    float* fsm   = dyn;                     // 64*132
    float* weffT = fsm + TSn * FSTRIDE;     // 80*132 (k-major)
    float* h1sm  = weffT + H1n * WS;        // 64*84
    float* w3T   = h1sm + TSn * H1S;        // 40*80  (k-major)

    __shared__ float qsm[Fn];
    __shared__ float qprem[H1n];
    __shared__ float w4sm[H2n];
    __shared__ float b3sm[H2n];
    __shared__ float psm[4 * TSn];
    __shared__ float wsm[TSn];
    __shared__ float s_m, s_l, s_scale, s_b4;

    const int b   = blockIdx.x;
    const int tid = threadIdx.x;
    const uint32_t fsm_base = smem_u32(fsm);
    const float* factsb = facts + (size_t)b * Sn * Fn;

    // ---- kick off async load of facts tile 0 ----
#pragma unroll
    for (int it = 0; it < 8; it++) {
        const int idx = it * 256 + tid;
        const int row = idx >> 5, c4 = idx & 31;
        cpa16(fsm_base + (uint32_t)(row * FSTRIDE + c4 * 4) * 4u,
              factsb + idx * 4);
    }
    CPA_COMMIT();

    // ---- prologue ----
    if (tid < Fn) qsm[tid] = query[b * Fn + tid];
    if (tid == 0) { s_m = -CUDART_INF_F; s_l = 0.f; s_b4 = b4[0]; }
    if (tid < H2n) { w4sm[tid] = W4[tid]; b3sm[tid] = b3[tid]; }
    for (int i = tid; i < H1n * H2n; i += 256) {   // w3T[h2][k] = W3[k][h2]
        const int h2 = i % H2n, k = i / H2n;
        w3T[h2 * W3S + k] = W3[i];
    }
    __syncthreads();

    float qv = 0.f;
    if (tid < Fn) {                     // q = PReLU(query@W1+b1)
        float a0 = b1[tid], a1 = 0.f, a2 = 0.f, a3 = 0.f;
#pragma unroll 4
        for (int k = 0; k < Fn; k += 4) {
            a0 = fmaf(qsm[k + 0], W1[(k + 0) * Fn + tid], a0);
            a1 = fmaf(qsm[k + 1], W1[(k + 1) * Fn + tid], a1);
            a2 = fmaf(qsm[k + 2], W1[(k + 2) * Fn + tid], a2);
            a3 = fmaf(qsm[k + 3], W1[(k + 3) * Fn + tid], a3);
        }
        const float acc = (a0 + a1) + (a2 + a3);
        qv = (acc >= 0.f) ? acc : alpha[tid] * acc;
    }
    __syncthreads();
    if (tid < Fn) qsm[tid] = qv;
    __syncthreads();

    if (tid < H1n) {                    // qpre
        float a0 = b2[tid], a1 = 0.f;
#pragma unroll 4
        for (int k = 0; k < Fn; k += 2) {
            a0 = fmaf(qsm[k+0], W2[(k+0)*H1n + tid] + W2[(2*Fn + k+0)*H1n + tid], a0);
            a1 = fmaf(qsm[k+1], W2[(k+1)*H1n + tid] + W2[(2*Fn + k+1)*H1n + tid], a1);
        }
        qprem[tid] = a0 + a1;
    }
    for (int i = tid; i < Fn * H1n; i += 256) {    // weffT (k-major)
        const int k = i / H1n, h = i - k * H1n;
        const float wbc = W2[(Fn + k) * H1n + h] - W2[(2 * Fn + k) * H1n + h];
        const float wd  = W2[(3 * Fn + k) * H1n + h];
        weffT[h * WS + k] = fmaf(qsm[k], wd, wbc);
    }
    CPA_WAIT0();
    __syncthreads();

    // low crew (tid<128): GEMM1 8x5. ty=tid&7 (rows ty+8i), tx=tid>>3 (cols tx*5..+4)
    const int ty = tid & 7;
    const int tx = tid >> 3;
    // high crew (tid>=128): epilogue feature + GEMM2 4x5
    const int ctid = tid & 127;
    const int rowg = ctid & 15;     // GEMM2 rows rowg*4..+3
    const int colg = ctid >> 4;     // GEMM2 cols colg*5..+4 (of 40)

    float racc = 0.f;

    for (int t = 0; t < NTn; t++) {
        // ================= phase A: GEMM1(t) [low] || epilogue(t-1) [high] ==
        if (tid < 128) {
            unsigned long long acc2[8][5];
#pragma unroll
            for (int j = 0; j < 5; j++) {
                const unsigned long long z = pk2(qprem[tx * 5 + j], 0.f);
#pragma unroll
                for (int i = 0; i < 8; i++) acc2[i][j] = z;
            }
            const float* fr = fsm + ty * FSTRIDE;
            const float* wb = weffT + (tx * 5) * WS;
#pragma unroll 1
            for (int k = 0; k < Fn; k += 4) {
                ulonglong2 bv[5];
#pragma unroll
                for (int j = 0; j < 5; j++)
                    bv[j] = *(const ulonglong2*)(wb + j * WS + k);
#pragma unroll
                for (int i = 0; i < 8; i++) {
                    const ulonglong2 av = *(const ulonglong2*)(fr + (8 * i) * FSTRIDE + k);
#pragma unroll
                    for (int j = 0; j < 5; j++) {
                        FMA2(acc2[i][j], av.x, bv[j].x);
                        FMA2(acc2[i][j], av.y, bv[j].y);
                    }
                }
            }
#pragma unroll
            for (int i = 0; i < 8; i++) {
                float* hb = h1sm + (ty + 8 * i) * H1S + tx * 5;
#pragma unroll
                for (int j = 0; j < 5; j++) {
                    const float2 v = upk2(acc2[i][j]);
                    hb[j] = fsigmoid(v.x + v.y);
                }
            }
        } else if (t > 0) {
            // epilogue for tile t-1 (reads wsm(t-1), s_scale(t-1), global facts)
            const float* fb = factsb + (size_t)((t - 1) * TSn) * Fn + ctid;
            float a0 = racc * s_scale, a1 = 0.f, a2 = 0.f, a3 = 0.f;
#pragma unroll 4
            for (int s = 0; s < TSn; s += 4) {
                a0 = fmaf(wsm[s + 0], fb[(size_t)(s + 0) * Fn], a0);
                a1 = fmaf(wsm[s + 1], fb[(size_t)(s + 1) * Fn], a1);
                a2 = fmaf(wsm[s + 2], fb[(size_t)(s + 2) * Fn], a2);
                a3 = fmaf(wsm[s + 3], fb[(size_t)(s + 3) * Fn], a3);
            }
            racc = (a0 + a1) + (a2 + a3);
        }
        __syncthreads();   // S1: h1 ready; fsm(t) reads done; epilogue done

        // ================= phase B: prefetch [low] || GEMM2(t) [high] =======
        if (tid < 128) {
            if (t + 1 < NTn) {
                const float* nsrc = factsb + (size_t)(t + 1) * TSn * Fn;
#pragma unroll
                for (int it = 0; it < 16; it++) {
                    const int idx = it * 128 + tid;
                    const int row = idx >> 5, c4 = idx & 31;
                    cpa16(fsm_base + (uint32_t)(row * FSTRIDE + c4 * 4) * 4u,
                          nsrc + idx * 4);
                }
                CPA_COMMIT();
            }
        } else {
            unsigned long long acc2[4][5];
#pragma unroll
            for (int j = 0; j < 5; j++) {
                const unsigned long long z = pk2(b3sm[colg * 5 + j], 0.f);
#pragma unroll
                for (int i = 0; i < 4; i++) acc2[i][j] = z;
            }
            const float* hr = h1sm + (rowg * 4) * H1S;
            const float* wc = w3T + (colg * 5) * W3S;
#pragma unroll 2
            for (int k = 0; k < H1n; k += 4) {
                ulonglong2 av[4], bv[5];
#pragma unroll
                for (int i = 0; i < 4; i++)
                    av[i] = *(const ulonglong2*)(hr + i * H1S + k);
#pragma unroll
                for (int j = 0; j < 5; j++)
                    bv[j] = *(const ulonglong2*)(wc + j * W3S + k);
#pragma unroll
                for (int i = 0; i < 4; i++)
#pragma unroll
                    for (int j = 0; j < 5; j++) {
                        FMA2(acc2[i][j], av[i].x, bv[j].x);
                        FMA2(acc2[i][j], av[i].y, bv[j].y);
                    }
            }
#pragma unroll
            for (int i = 0; i < 4; i++) {
                float p = 0.f;
#pragma unroll
                for (int j = 0; j < 5; j++) {
                    const float2 v = upk2(acc2[i][j]);
                    p = fmaf(fsigmoid(v.x + v.y), w4sm[colg * 5 + j], p);
                }
                p += __shfl_xor_sync(0xffffffffu, p, 16);   // colg pair
                if ((ctid & 16) == 0)
                    psm[(ctid >> 5) * TSn + rowg * 4 + i] = p;
            }
        }
        __syncthreads();   // S2: psm ready

        // ================= phase C: fused softmax (warp 0 only) =============
        if (tid < 32) {
            float sa = psm[tid]      + psm[TSn + tid]      + psm[2*TSn + tid]
                     + psm[3*TSn + tid]      + s_b4;
            float sb = psm[tid + 32] + psm[TSn + tid + 32] + psm[2*TSn + tid + 32]
                     + psm[3*TSn + tid + 32] + s_b4;
            const int mb = b * Sn + t * TSn;
            sa = (mask[mb + tid]      == 1) ? sa : PADV;
            sb = (mask[mb + tid + 32] == 1) ? sb : PADV;
            float m4 = fmaxf(sa, sb);
#pragma unroll
            for (int off = 16; off; off >>= 1)
                m4 = fmaxf(m4, __shfl_xor_sync(0xffffffffu, m4, off));
            const float nm = fmaxf(s_m, m4);
            const float scale = __expf(s_m - nm);     // 0 on first tile
            const float wa = __expf(sa - nm);
            const float wb2 = __expf(sb - nm);
            wsm[tid] = wa;
            wsm[tid + 32] = wb2;
            float ws = wa + wb2;
#pragma unroll
            for (int off = 16; off; off >>= 1)
                ws += __shfl_xor_sync(0xffffffffu, ws, off);
            if (tid == 0) {
                s_l = s_l * scale + ws;
                s_m = nm;
                s_scale = scale;
            }
        }
        CPA_WAIT0();
        __syncthreads();   // S3: wsm/s_scale ready; fsm(t+1) landed
    }

    // ---- final epilogue (tile NTn-1) + output (high crew) ----
    if (tid >= 128) {
        const float* fb = factsb + (size_t)((NTn - 1) * TSn) * Fn + ctid;
        float a0 = racc * s_scale, a1 = 0.f, a2 = 0.f, a3 = 0.f;
#pragma unroll 4
        for (int s = 0; s < TSn; s += 4) {
            a0 = fmaf(wsm[s + 0], fb[(size_t)(s + 0) * Fn], a0);
            a1 = fmaf(wsm[s + 1], fb[(size_t)(s + 1) * Fn], a1);
            a2 = fmaf(wsm[s + 2], fb[(size_t)(s + 2) * Fn], a2);
            a3 = fmaf(wsm[s + 3], fb[(size_t)(s + 3) * Fn], a3);
        }
        racc = (a0 + a1) + (a2 + a3);
        out[b * Fn + ctid] = racc / s_l;
    }
}

// ---------------------------------------------------------------------------
extern "C" void kernel_launch(void* const* d_in, const int* in_sizes, int n_in,
                              void* d_out, int out_size)
{
    const float* query = (const float*)d_in[0];
    const float* facts = (const float*)d_in[1];
    const int*   mask  = (const int*)  d_in[2];
    const float* W1    = (const float*)d_in[3];
    const float* b1    = (const float*)d_in[4];
    const float* alpha = (const float*)d_in[5];
    const float* W2    = (const float*)d_in[6];
    const float* b2    = (const float*)d_in[7];
    const float* W3    = (const float*)d_in[8];
    const float* b3    = (const float*)d_in[9];
    const float* W4    = (const float*)d_in[10];
    const float* b4    = (const float*)d_in[11];
    float* out = (float*)d_out;

    const int dyn_smem =
        (TSn * FSTRIDE + H1n * WS + TSn * H1S + H2n * W3S) * (int)sizeof(float); // 110336 B
    cudaFuncSetAttribute(din_kernel,
                         cudaFuncAttributeMaxDynamicSharedMemorySize, dyn_smem);

    din_kernel<<<Bn, 256, dyn_smem>>>(query, facts, mask, W1, b1, alpha,
                                      W2, b2, W3, b3, W4, b4, out);
}

// round 15
// speedup vs baseline: 1.3321x; 1.1363x over previous
#include <cuda_runtime.h>
#include <math_constants.h>
#include <stdint.h>

// attention_FCN: B=512, S=512, F=128, H1=80, H2=40
// din@W2 = qpre(b) + f @ Weff(b),  Weff = (W2b - W2c) + diag(q_b) @ W2d
// Round 15: R12 compute shapes (GEMM1 4x5 x 256thr, GEMM2 4x5 x 128thr,
// 2 CTA/SM) with a restructured timeline:
//  - epilogue(t-1) on high 128 threads CONCURRENT with GEMM2(t) on low 128
//    (wsm / s_scale double-buffered by tile parity)
//  - fused single-warp softmax (no intermediate syncs)
//  - 3 CTA-wide syncs per tile (was 6)

#define Bn   512
#define Sn   512
#define Fn   128
#define H1n  80
#define H2n  40
#define TSn  64
#define NTn  (Sn / TSn)
#define FSTRIDE 132
#define WS      132
#define H1S     84
#define W3S     80
#define PADV (-4294967295.0f)

__device__ __forceinline__ unsigned long long pk2(float lo, float hi) {
    unsigned long long r;
    asm("mov.b64 %0, {%1,%2};" : "=l"(r) : "f"(lo), "f"(hi));
    return r;
}
__device__ __forceinline__ float2 upk2(unsigned long long v) {
    float2 r;
    asm("mov.b64 {%0,%1}, %2;" : "=f"(r.x), "=f"(r.y) : "l"(v));
    return r;
}
#define FMA2(d, a, b) \
    asm("fma.rn.f32x2 %0, %1, %2, %0;" : "+l"(d) : "l"(a), "l"(b))

__device__ __forceinline__ float fsigmoid(float x) {
    return __fdividef(1.f, 1.f + __expf(-x));
}
__device__ __forceinline__ uint32_t smem_u32(const void* p) {
    uint32_t a;
    asm("{ .reg .u64 t; cvta.to.shared.u64 t, %1; cvt.u32.u64 %0, t; }"
        : "=r"(a) : "l"(p));
    return a;
}
__device__ __forceinline__ void cpa16(uint32_t dst, const float* src) {
    asm volatile("cp.async.cg.shared.global [%0], [%1], 16;"
                 :: "r"(dst), "l"(src) : "memory");
}
#define CPA_COMMIT() asm volatile("cp.async.commit_group;" ::: "memory")
#define CPA_WAIT0()  asm volatile("cp.async.wait_group 0;" ::: "memory")

// ---------------------------------------------------------------------------
__global__ __launch_bounds__(256, 2) void din_kernel(
    const float* __restrict__ query,
    const float* __restrict__ facts,
    const int*   __restrict__ mask,
    const float* __restrict__ W1,
    const float* __restrict__ b1,
    const float* __restrict__ alpha,
    const float* __restrict__ W2,
    const float* __restrict__ b2,
    const float* __restrict__ W3,
    const float* __restrict__ b3,
    const float* __restrict__ W4,
    const float* __restrict__ b4,
    float* __restrict__ out)
{
    extern __shared__ float dyn[];
    float* fsm   = dyn;                     // 64*132
    float* weffT = fsm + TSn * FSTRIDE;     // 80*132 (k-major)
    float* h1sm  = weffT + H1n * WS;        // 64*84
    float* w3T   = h1sm + TSn * H1S;        // 40*80  (k-major)

    __shared__ float qsm[Fn];
    __shared__ float qprem[H1n];
    __shared__ float w4sm[H2n];
    __shared__ float b3sm[H2n];
    __shared__ float psm[4 * TSn];
    __shared__ float wsmb[2][TSn];          // softmax weights, tile-parity
    __shared__ float sscb[2];               // s_scale, tile-parity
    __shared__ float s_m, s_l, s_b4;

    const int b   = blockIdx.x;
    const int tid = threadIdx.x;
    const uint32_t fsm_base = smem_u32(fsm);
    const float* factsb = facts + (size_t)b * Sn * Fn;

    // ---- kick off async load of facts tile 0 ----
#pragma unroll
    for (int it = 0; it < 8; it++) {
        const int idx = it * 256 + tid;
        const int row = idx >> 5, c4 = idx & 31;
        cpa16(fsm_base + (uint32_t)(row * FSTRIDE + c4 * 4) * 4u,
              factsb + idx * 4);
    }
    CPA_COMMIT();

    // ---- prologue ----
    if (tid < Fn) qsm[tid] = query[b * Fn + tid];
    if (tid == 0) { s_m = -CUDART_INF_F; s_l = 0.f; s_b4 = b4[0]; }
    if (tid < H2n) { w4sm[tid] = W4[tid]; b3sm[tid] = b3[tid]; }
    for (int i = tid; i < H1n * H2n; i += 256) {   // w3T[h2][k] = W3[k][h2]
        const int h2 = i % H2n, k = i / H2n;
        w3T[h2 * W3S + k] = W3[i];
    }
    __syncthreads();

    float qv = 0.f;
    if (tid < Fn) {                     // q = PReLU(query@W1+b1)
        float a0 = b1[tid], a1 = 0.f, a2 = 0.f, a3 = 0.f;
#pragma unroll 4
        for (int k = 0; k < Fn; k += 4) {
            a0 = fmaf(qsm[k + 0], W1[(k + 0) * Fn + tid], a0);
            a1 = fmaf(qsm[k + 1], W1[(k + 1) * Fn + tid], a1);
            a2 = fmaf(qsm[k + 2], W1[(k + 2) * Fn + tid], a2);
            a3 = fmaf(qsm[k + 3], W1[(k + 3) * Fn + tid], a3);
        }
        const float acc = (a0 + a1) + (a2 + a3);
        qv = (acc >= 0.f) ? acc : alpha[tid] * acc;
    }
    __syncthreads();
    if (tid < Fn) qsm[tid] = qv;
    __syncthreads();

    if (tid < H1n) {                    // qpre
        float a0 = b2[tid], a1 = 0.f;
#pragma unroll 4
        for (int k = 0; k < Fn; k += 2) {
            a0 = fmaf(qsm[k+0], W2[(k+0)*H1n + tid] + W2[(2*Fn + k+0)*H1n + tid], a0);
            a1 = fmaf(qsm[k+1], W2[(k+1)*H1n + tid] + W2[(2*Fn + k+1)*H1n + tid], a1);
        }
        qprem[tid] = a0 + a1;
    }
    for (int i = tid; i < Fn * H1n; i += 256) {    // weffT (k-major)
        const int k = i / H1n, h = i - k * H1n;
        const float wbc = W2[(Fn + k) * H1n + h] - W2[(2 * Fn + k) * H1n + h];
        const float wd  = W2[(3 * Fn + k) * H1n + h];
        weffT[h * WS + k] = fmaf(qsm[k], wd, wbc);
    }
    CPA_WAIT0();
    __syncthreads();

    const int tx = tid & 15;      // GEMM1 cols tx*5..+4
    const int ty = tid >> 4;      // GEMM1 rows ty*4..+3
    const int ctid = tid & 127;   // low: GEMM2 index / high: epilogue feature
    const int rowg = ctid & 15;   // GEMM2 rows rowg*4..+3
    const int colg = ctid >> 4;   // GEMM2 cols colg*5..+4

    float racc = 0.f;             // epilogue accumulator (high crew)

    for (int t = 0; t < NTn; t++) {
        // ============ phase A: GEMM1(t) on all 256 threads =================
        {
            unsigned long long acc2[4][5];
#pragma unroll
            for (int i = 0; i < 4; i++)
#pragma unroll
                for (int j = 0; j < 5; j++)
                    acc2[i][j] = pk2(qprem[tx * 5 + j], 0.f);

            const float* fr = fsm   + (ty * 4) * FSTRIDE;
            const float* wb = weffT + (tx * 5) * WS;
#pragma unroll 2
            for (int k = 0; k < Fn; k += 4) {
                ulonglong2 av[4], bv[5];
#pragma unroll
                for (int i = 0; i < 4; i++)
                    av[i] = *(const ulonglong2*)(fr + i * FSTRIDE + k);
#pragma unroll
                for (int j = 0; j < 5; j++)
                    bv[j] = *(const ulonglong2*)(wb + j * WS + k);
#pragma unroll
                for (int i = 0; i < 4; i++)
#pragma unroll
                    for (int j = 0; j < 5; j++) {
                        FMA2(acc2[i][j], av[i].x, bv[j].x);
                        FMA2(acc2[i][j], av[i].y, bv[j].y);
                    }
            }
#pragma unroll
            for (int i = 0; i < 4; i++)
#pragma unroll
                for (int j = 0; j < 5; j++) {
                    const float2 v = upk2(acc2[i][j]);
                    h1sm[(ty * 4 + i) * H1S + tx * 5 + j] = fsigmoid(v.x + v.y);
                }
        }
        __syncthreads();   // S1: h1 ready; fsm(t) reads done

        // ===== phase B: GEMM2(t) [low 128]  ||  prefetch + epilogue(t-1) ====
        if (tid < 128) {
            unsigned long long acc2[4][5];
#pragma unroll
            for (int j = 0; j < 5; j++) {
                const unsigned long long z = pk2(b3sm[colg * 5 + j], 0.f);
#pragma unroll
                for (int i = 0; i < 4; i++) acc2[i][j] = z;
            }
            const float* hr = h1sm + (rowg * 4) * H1S;
            const float* wc = w3T + (colg * 5) * W3S;
#pragma unroll 2
            for (int k = 0; k < H1n; k += 4) {
                ulonglong2 av[4], bv[5];
#pragma unroll
                for (int i = 0; i < 4; i++)
                    av[i] = *(const ulonglong2*)(hr + i * H1S + k);
#pragma unroll
                for (int j = 0; j < 5; j++)
                    bv[j] = *(const ulonglong2*)(wc + j * W3S + k);
#pragma unroll
                for (int i = 0; i < 4; i++)
#pragma unroll
                    for (int j = 0; j < 5; j++) {
                        FMA2(acc2[i][j], av[i].x, bv[j].x);
                        FMA2(acc2[i][j], av[i].y, bv[j].y);
                    }
            }
#pragma unroll
            for (int i = 0; i < 4; i++) {
                float p = 0.f;
#pragma unroll
                for (int j = 0; j < 5; j++) {
                    const float2 v = upk2(acc2[i][j]);
                    p = fmaf(fsigmoid(v.x + v.y), w4sm[colg * 5 + j], p);
                }
                p += __shfl_xor_sync(0xffffffffu, p, 16);   // colg pair
                if ((ctid & 16) == 0)
                    psm[(ctid >> 5) * TSn + rowg * 4 + i] = p;
            }
        } else {
            // prefetch facts tile t+1 (fsm reads finished at S1)
            if (t + 1 < NTn) {
                const float* nsrc = factsb + (size_t)(t + 1) * TSn * Fn;
#pragma unroll
                for (int it = 0; it < 16; it++) {
                    const int idx = it * 128 + ctid;
                    const int row = idx >> 5, c4 = idx & 31;
                    cpa16(fsm_base + (uint32_t)(row * FSTRIDE + c4 * 4) * 4u,
                          nsrc + idx * 4);
                }
                CPA_COMMIT();
            }
            // epilogue for tile t-1 (buffered weights, global facts via L2)
            if (t > 0) {
                const float* wp = wsmb[(t - 1) & 1];
                const float  sc = sscb[(t - 1) & 1];
                const float* fb = factsb + (size_t)((t - 1) * TSn) * Fn + ctid;
                float a0 = racc * sc, a1 = 0.f, a2 = 0.f, a3 = 0.f;
#pragma unroll 4
                for (int s = 0; s < TSn; s += 4) {
                    a0 = fmaf(wp[s + 0], fb[(size_t)(s + 0) * Fn], a0);
                    a1 = fmaf(wp[s + 1], fb[(size_t)(s + 1) * Fn], a1);
                    a2 = fmaf(wp[s + 2], fb[(size_t)(s + 2) * Fn], a2);
                    a3 = fmaf(wp[s + 3], fb[(size_t)(s + 3) * Fn], a3);
                }
                racc = (a0 + a1) + (a2 + a3);
            }
        }
        __syncthreads();   // S2: psm ready; epilogue(t-1) done

        // ============ phase C: fused softmax (warp 0 only) =================
        if (tid < 32) {
            float sa = psm[tid]      + psm[TSn + tid]      + psm[2*TSn + tid]
                     + psm[3*TSn + tid]      + s_b4;
            float sb = psm[tid + 32] + psm[TSn + tid + 32] + psm[2*TSn + tid + 32]
                     + psm[3*TSn + tid + 32] + s_b4;
            const int mb = b * Sn + t * TSn;
            sa = (mask[mb + tid]      == 1) ? sa : PADV;
            sb = (mask[mb + tid + 32] == 1) ? sb : PADV;
            float m4 = fmaxf(sa, sb);
#pragma unroll
            for (int off = 16; off; off >>= 1)
                m4 = fmaxf(m4, __shfl_xor_sync(0xffffffffu, m4, off));
            const float nm = fmaxf(s_m, m4);
            const float scale = __expf(s_m - nm);     // 0 on first tile
            const float wa = __expf(sa - nm);
            const float wb2 = __expf(sb - nm);
            wsmb[t & 1][tid]      = wa;
            wsmb[t & 1][tid + 32] = wb2;
            float ws = wa + wb2;
#pragma unroll
            for (int off = 16; off; off >>= 1)
                ws += __shfl_xor_sync(0xffffffffu, ws, off);
            if (tid == 0) {
                s_l = s_l * scale + ws;
                s_m = nm;
                sscb[t & 1] = scale;
            }
        }
        CPA_WAIT0();
        __syncthreads();   // S3: wsm(t)/scale(t) ready; fsm(t+1) landed
    }

    // ---- final epilogue (tile NTn-1) + output (high crew) ----
    if (tid >= 128) {
        const float* wp = wsmb[(NTn - 1) & 1];
        const float  sc = sscb[(NTn - 1) & 1];
        const float* fb = factsb + (size_t)((NTn - 1) * TSn) * Fn + ctid;
        float a0 = racc * sc, a1 = 0.f, a2 = 0.f, a3 = 0.f;
#pragma unroll 4
        for (int s = 0; s < TSn; s += 4) {
            a0 = fmaf(wp[s + 0], fb[(size_t)(s + 0) * Fn], a0);
            a1 = fmaf(wp[s + 1], fb[(size_t)(s + 1) * Fn], a1);
            a2 = fmaf(wp[s + 2], fb[(size_t)(s + 2) * Fn], a2);
            a3 = fmaf(wp[s + 3], fb[(size_t)(s + 3) * Fn], a3);
        }
        racc = (a0 + a1) + (a2 + a3);
        out[b * Fn + ctid] = racc / s_l;
    }
}

// ---------------------------------------------------------------------------
extern "C" void kernel_launch(void* const* d_in, const int* in_sizes, int n_in,
                              void* d_out, int out_size)
{
    const float* query = (const float*)d_in[0];
    const float* facts = (const float*)d_in[1];
    const int*   mask  = (const int*)  d_in[2];
    const float* W1    = (const float*)d_in[3];
    const float* b1    = (const float*)d_in[4];
    const float* alpha = (const float*)d_in[5];
    const float* W2    = (const float*)d_in[6];
    const float* b2    = (const float*)d_in[7];
    const float* W3    = (const float*)d_in[8];
    const float* b3    = (const float*)d_in[9];
    const float* W4    = (const float*)d_in[10];
    const float* b4    = (const float*)d_in[11];
    float* out = (float*)d_out;

    const int dyn_smem =
        (TSn * FSTRIDE + H1n * WS + TSn * H1S + H2n * W3S) * (int)sizeof(float); // 110336 B
    cudaFuncSetAttribute(din_kernel,
                         cudaFuncAttributeMaxDynamicSharedMemorySize, dyn_smem);

    din_kernel<<<Bn, 256, dyn_smem>>>(query, facts, mask, W1, b1, alpha,
                                      W2, b2, W3, b3, W4, b4, out);
}